// round 1
// baseline (speedup 1.0000x reference)
#include <cuda_runtime.h>
#include <math.h>

// Problem dims
#define F_TOT 320          // B*T frames
#define T_STEPS 20
#define B_SZ 16
#define CIN 64
#define CH 128
#define HW 1024            // 32*32
#define KTOT 576           // CIN*9

// Conv tiling
#define BM 64              // pixels per block (2 rows x 32 cols)
#define BN 128             // out channels per block (all)
#define BK 16

// -------- scratch (static device globals; no runtime alloc) --------
__device__ float g_y[(size_t)F_TOT * CH * HW];   // conv output, 168 MB
__device__ float g_wT[KTOT * CH];                // weights transposed [k][n]
__device__ float g_psum[F_TOT];                  // per-(b,t) sum pool
__device__ int   g_pmax[F_TOT];                  // per-(b,t) max pool (ordered-int encoded)
__device__ float g_att[F_TOT];                   // attention weights

// ordered-int encode/decode for float atomicMax
__device__ __forceinline__ int enc_f(float v) {
    int ix = __float_as_int(v);
    return ix >= 0 ? ix : (ix ^ 0x7fffffff);
}
__device__ __forceinline__ float dec_f(int e) {
    int ix = e >= 0 ? e : (e ^ 0x7fffffff);
    return __int_as_float(ix);
}

// -------- kernel 1: reset pools --------
__global__ void init_kernel() {
    int i = blockIdx.x * blockDim.x + threadIdx.x;
    if (i < F_TOT) {
        g_psum[i] = 0.f;
        g_pmax[i] = 0x80000000;  // INT_MIN
    }
}

// -------- kernel 2: transpose weights OIHW -> [k=ci*9+ky*3+kx][n] --------
__global__ void wt_kernel(const float* __restrict__ w) {
    int i = blockIdx.x * blockDim.x + threadIdx.x;   // i = k*CH + n
    if (i < KTOT * CH) {
        int k = i / CH;
        int n = i - k * CH;
        g_wT[i] = w[n * KTOT + k];
    }
}

// -------- kernel 3: implicit-GEMM conv + bias + pool epilogue --------
// grid = (16 row-stripes, 320 frames), 256 threads
__global__ __launch_bounds__(256) void conv_kernel(const float* __restrict__ data,
                                                   const float* __restrict__ bias) {
    __shared__ float As[BK][BM];        // input patches [kk][pixel]
    __shared__ float Bs[BK][BN];        // weights       [kk][n]
    __shared__ float red_s[8], red_m[8];

    const int tid = threadIdx.x;
    const int tx = tid & 15;            // n-group: channels tx*8 .. tx*8+7
    const int ty = tid >> 4;            // m-group: pixels ty*4 .. ty*4+3
    const int f = blockIdx.y;
    const int row0 = blockIdx.x * 2;    // 2 output rows per block

    const float* __restrict__ in = data + (size_t)f * (CIN * HW);

    float acc[4][8];
#pragma unroll
    for (int i = 0; i < 4; i++)
#pragma unroll
        for (int j = 0; j < 8; j++) acc[i][j] = 0.f;

    const float4* __restrict__ wt4 = (const float4*)g_wT;

    for (int k0 = 0; k0 < KTOT; k0 += BK) {
        // ---- gather A (im2col) into regs ----
        float a_r[4];
#pragma unroll
        for (int i = 0; i < 4; i++) {
            int e  = tid + i * 256;          // 0..1023
            int kk = e >> 6;
            int m  = e & 63;
            int k  = k0 + kk;
            int ci = k / 9;
            int rem = k - ci * 9;
            int ky = rem / 3;
            int kx = rem - ky * 3;
            int py = row0 + (m >> 5) + ky - 1;
            int px = (m & 31) + kx - 1;
            float v = 0.f;
            if ((unsigned)py < 32u && (unsigned)px < 32u)
                v = __ldg(&in[ci * HW + py * 32 + px]);
            a_r[i] = v;
        }
        // ---- load B (coalesced float4) into regs ----
        float4 b_r0 = wt4[k0 * 32 + tid];
        float4 b_r1 = wt4[k0 * 32 + tid + 256];

        __syncthreads();   // previous compute done before overwriting smem
#pragma unroll
        for (int i = 0; i < 4; i++) {
            int e = tid + i * 256;
            As[e >> 6][e & 63] = a_r[i];
        }
        ((float4*)Bs)[tid]       = b_r0;
        ((float4*)Bs)[tid + 256] = b_r1;
        __syncthreads();

        // ---- compute 4x8 microtile over BK ----
#pragma unroll
        for (int kk = 0; kk < BK; kk++) {
            float4 a  = *(const float4*)&As[kk][ty * 4];
            float4 b0 = *(const float4*)&Bs[kk][tx * 8];
            float4 b1 = *(const float4*)&Bs[kk][tx * 8 + 4];
            float av[4] = {a.x, a.y, a.z, a.w};
            float bv[8] = {b0.x, b0.y, b0.z, b0.w, b1.x, b1.y, b1.z, b1.w};
#pragma unroll
            for (int i = 0; i < 4; i++)
#pragma unroll
                for (int j = 0; j < 8; j++)
                    acc[i][j] = fmaf(av[i], bv[j], acc[i][j]);
        }
    }

    // ---- epilogue: bias, store, pool ----
    float bvals[8];
#pragma unroll
    for (int j = 0; j < 8; j++) bvals[j] = __ldg(&bias[tx * 8 + j]);

    float lsum = 0.f, lmax = -1e30f;
    const size_t base = (size_t)f * (CH * HW) + row0 * 32 + ty * 4;
#pragma unroll
    for (int j = 0; j < 8; j++) {
        int n = tx * 8 + j;
        float4 o;
        float* op = (float*)&o;
#pragma unroll
        for (int i = 0; i < 4; i++) {
            float v = acc[i][j] + bvals[j];
            op[i] = v;
            lsum += v;
            lmax = fmaxf(lmax, v);
        }
        *(float4*)&g_y[base + (size_t)n * HW] = o;
    }

    // block reduce sum/max
#pragma unroll
    for (int off = 16; off; off >>= 1) {
        lsum += __shfl_down_sync(0xffffffff, lsum, off);
        lmax = fmaxf(lmax, __shfl_down_sync(0xffffffff, lmax, off));
    }
    if ((tid & 31) == 0) {
        red_s[tid >> 5] = lsum;
        red_m[tid >> 5] = lmax;
    }
    __syncthreads();
    if (tid == 0) {
        float s = 0.f, mx = -1e30f;
#pragma unroll
        for (int w = 0; w < 8; w++) {
            s += red_s[w];
            mx = fmaxf(mx, red_m[w]);
        }
        atomicAdd(&g_psum[f], s);
        atomicMax(&g_pmax[f], enc_f(mx));
    }
}

// -------- kernel 4: temporal attention (tiny MLP) --------
__global__ void att_kernel(const float* __restrict__ w1,   // [5,20]
                           const float* __restrict__ w2) { // [20,5]
    int tid = threadIdx.x;
    if (tid >= F_TOT) return;
    int b = tid / T_STEPS;
    int t = tid - b * T_STEPS;

    float avgv[T_STEPS], mxv[T_STEPS];
#pragma unroll
    for (int tt = 0; tt < T_STEPS; tt++) {
        avgv[tt] = g_psum[b * T_STEPS + tt] * (1.f / (float)(CH * HW));
        mxv[tt]  = dec_f(g_pmax[b * T_STEPS + tt]);
    }
    float o = 0.f;
#pragma unroll
    for (int j = 0; j < 5; j++) {
        float ha = 0.f, hm = 0.f;
#pragma unroll
        for (int tt = 0; tt < T_STEPS; tt++) {
            float w = w1[j * T_STEPS + tt];
            ha = fmaf(avgv[tt], w, ha);
            hm = fmaf(mxv[tt], w, hm);
        }
        ha = fmaxf(ha, 0.f);
        hm = fmaxf(hm, 0.f);
        o = fmaf(ha + hm, w2[t * 5 + j], o);
    }
    g_att[tid] = 1.f / (1.f + expf(-o));
}

// -------- kernel 5: LIF recurrence --------
__global__ __launch_bounds__(256) void lif_kernel(float* __restrict__ out) {
    int idx = blockIdx.x * blockDim.x + threadIdx.x;   // < B*CH*HW = 2097152
    int b = idx >> 17;            // / (CH*HW)
    int r = idx & 131071;         // ch*HW + pix
    float h = 0.f;
#pragma unroll
    for (int t = 0; t < T_STEPS; t++) {
        int f = b * T_STEPS + t;
        size_t off = (size_t)f * (CH * HW) + r;
        float v = g_y[off] * g_att[f];
        float u = fmaf(h, 0.3f, v);     // ALPHA = 0.3
        float s = (u >= 0.6f) ? 1.f : 0.f;  // VTH = 0.6
        out[off] = s;
        h = u * (1.f - s);              // hard reset, VRESET = 0
    }
}

// -------- launch --------
extern "C" void kernel_launch(void* const* d_in, const int* in_sizes, int n_in,
                              void* d_out, int out_size) {
    const float* data   = (const float*)d_in[0];  // [16,20,64,32,32]
    const float* conv_w = (const float*)d_in[1];  // [128,64,3,3]
    const float* conv_b = (const float*)d_in[2];  // [128]
    const float* mlp_w1 = (const float*)d_in[3];  // [5,20]
    const float* mlp_w2 = (const float*)d_in[4];  // [20,5]
    float* out = (float*)d_out;

    init_kernel<<<(F_TOT + 255) / 256, 256>>>();
    wt_kernel<<<(KTOT * CH + 255) / 256, 256>>>(conv_w);
    conv_kernel<<<dim3(16, F_TOT), 256>>>(data, conv_b);
    att_kernel<<<1, F_TOT>>>(mlp_w1, mlp_w2);
    lif_kernel<<<(B_SZ * CH * HW) / 256, 256>>>(out);
}

// round 2
// speedup vs baseline: 1.6101x; 1.6101x over previous
#include <cuda_runtime.h>
#include <math.h>

// Problem dims
#define F_TOT 320          // B*T frames
#define T_STEPS 20
#define B_SZ 16
#define CIN 64
#define CH 128
#define HW 1024            // 32*32
#define KTOT 576           // CIN*9

// Conv tiling
#define BM 128             // pixels per block (4 rows x 32 cols)
#define BN 128             // out channels per block (all)
#define BK 8

// -------- scratch (static device globals; no runtime alloc) --------
__device__ float g_y[(size_t)F_TOT * CH * HW];   // conv output, 168 MB
__device__ float g_wT[KTOT * CH];                // weights [r][ci][n]
__device__ float g_psum[F_TOT];                  // per-(b,t) sum pool
__device__ int   g_pmax[F_TOT];                  // per-(b,t) max pool (ordered-int)
__device__ float g_att[F_TOT];                   // attention weights

__device__ __forceinline__ int enc_f(float v) {
    int ix = __float_as_int(v);
    return ix >= 0 ? ix : (ix ^ 0x7fffffff);
}
__device__ __forceinline__ float dec_f(int e) {
    int ix = e >= 0 ? e : (e ^ 0x7fffffff);
    return __int_as_float(ix);
}

// -------- kernel 1: reset pools --------
__global__ void init_kernel() {
    int i = blockIdx.x * blockDim.x + threadIdx.x;
    if (i < F_TOT) {
        g_psum[i] = 0.f;
        g_pmax[i] = 0x80000000;  // INT_MIN
    }
}

// -------- kernel 2: weights OIHW -> [r=ky*3+kx][ci][n] --------
__global__ void wt_kernel(const float* __restrict__ w) {
    int i = blockIdx.x * blockDim.x + threadIdx.x;   // i = (r*64+ci)*128 + n
    if (i < KTOT * CH) {
        int k2 = i >> 7;          // r*64+ci
        int n  = i & 127;
        int r  = k2 >> 6;
        int ci = k2 & 63;
        g_wT[i] = w[n * KTOT + ci * 9 + r];
    }
}

// -------- kernel 3: implicit-GEMM conv + bias + pool epilogue --------
// grid = (8 row-stripes of 4 rows, 320 frames), 256 threads
// microtile 8x8 per thread, split 4+4 with stride 64 (bank-conflict free)
__global__ __launch_bounds__(256, 2) void conv_kernel(const float* __restrict__ data,
                                                      const float* __restrict__ bias) {
    __shared__ float As[2][BK][BM];   // 2 x 4KB
    __shared__ float Bs[2][BK][BN];   // 2 x 4KB
    __shared__ float red_s[8], red_m[8];

    const int tid = threadIdx.x;
    const int tx = tid & 15;          // n groups: {tx*4.., 64+tx*4..}
    const int ty = tid >> 4;          // m groups: {ty*4.., 64+ty*4..}
    const int f = blockIdx.y;
    const int row0 = blockIdx.x * 4;  // 4 output rows per block

    const float* __restrict__ in = data + (size_t)f * (CIN * HW);

    // A-gather fixed mapping: warp w fills As row kk=w, 128 m per row
    const int kkA  = tid >> 5;            // 0..7 (= ci offset within tile)
    const int mA   = (tid * 4) & 127;     // 0,4,...,124
    const int mrow = mA >> 5;
    const int mcol = mA & 31;

    float acc[8][8];
#pragma unroll
    for (int i = 0; i < 8; i++)
#pragma unroll
        for (int j = 0; j < 8; j++) acc[i][j] = 0.f;

    // prefetch regs
    float aP[4];
    float4 bP;

    // tile index rt in [0,72): r = rt>>3 (shift), ci0 = (rt&7)*8
#define LOAD_TILE(rt)                                                          \
    {                                                                          \
        int r_   = (rt) >> 3;                                                  \
        int ci0_ = ((rt) & 7) * 8;                                             \
        int dy_  = r_ / 3 - 1;                                                 \
        int dx_  = r_ % 3 - 1;                                                 \
        int py_  = row0 + mrow + dy_;                                          \
        int ci_  = ci0_ + kkA;                                                 \
        const float* p_ = in + ci_ * HW + py_ * 32 + mcol + dx_;               \
        bool rowok_ = (unsigned)py_ < 32u;                                     \
        _Pragma("unroll")                                                      \
        for (int i_ = 0; i_ < 4; i_++) {                                       \
            int px_ = mcol + dx_ + i_;                                         \
            aP[i_] = (rowok_ && (unsigned)px_ < 32u) ? __ldg(p_ + i_) : 0.f;   \
        }                                                                      \
        bP = *(const float4*)&g_wT[(r_ * 64 + ci0_) * 128 + tid * 4];          \
    }

    LOAD_TILE(0);

    int buf = 0;
    for (int rt = 0; rt < 72; rt++) {
        // commit prefetched tile to smem[buf]
        *(float4*)&As[buf][kkA][mA] = make_float4(aP[0], aP[1], aP[2], aP[3]);
        ((float4*)&Bs[buf][0][0])[tid] = bP;
        __syncthreads();

        if (rt + 1 < 72) LOAD_TILE(rt + 1);

#pragma unroll
        for (int kk = 0; kk < BK; kk++) {
            float4 a0 = *(const float4*)&As[buf][kk][ty * 4];
            float4 a1 = *(const float4*)&As[buf][kk][ty * 4 + 64];
            float4 b0 = *(const float4*)&Bs[buf][kk][tx * 4];
            float4 b1 = *(const float4*)&Bs[buf][kk][tx * 4 + 64];
            float av[8] = {a0.x, a0.y, a0.z, a0.w, a1.x, a1.y, a1.z, a1.w};
            float bv[8] = {b0.x, b0.y, b0.z, b0.w, b1.x, b1.y, b1.z, b1.w};
#pragma unroll
            for (int i = 0; i < 8; i++)
#pragma unroll
                for (int j = 0; j < 8; j++)
                    acc[i][j] = fmaf(av[i], bv[j], acc[i][j]);
        }
        buf ^= 1;
    }
#undef LOAD_TILE

    // ---- epilogue: bias, store, pool ----
    float bvals[8];
#pragma unroll
    for (int j = 0; j < 8; j++) {
        int n = (j < 4) ? tx * 4 + j : 64 + tx * 4 + (j - 4);
        bvals[j] = __ldg(&bias[n]);
    }

    float lsum = 0.f, lmax = -1e30f;
    const size_t fb = (size_t)f * (CH * HW) + row0 * 32;
#pragma unroll
    for (int j = 0; j < 8; j++) {
        int n = (j < 4) ? tx * 4 + j : 64 + tx * 4 + (j - 4);
#pragma unroll
        for (int half = 0; half < 2; half++) {
            int m = ty * 4 + half * 64;
            float4 o;
            float* op = (float*)&o;
#pragma unroll
            for (int i = 0; i < 4; i++) {
                float v = acc[half * 4 + i][j] + bvals[j];
                op[i] = v;
                lsum += v;
                lmax = fmaxf(lmax, v);
            }
            *(float4*)&g_y[fb + (size_t)n * HW + m] = o;
        }
    }

    // block reduce sum/max
#pragma unroll
    for (int off = 16; off; off >>= 1) {
        lsum += __shfl_down_sync(0xffffffff, lsum, off);
        lmax = fmaxf(lmax, __shfl_down_sync(0xffffffff, lmax, off));
    }
    if ((tid & 31) == 0) {
        red_s[tid >> 5] = lsum;
        red_m[tid >> 5] = lmax;
    }
    __syncthreads();
    if (tid == 0) {
        float s = 0.f, mx = -1e30f;
#pragma unroll
        for (int w = 0; w < 8; w++) {
            s += red_s[w];
            mx = fmaxf(mx, red_m[w]);
        }
        atomicAdd(&g_psum[f], s);
        atomicMax(&g_pmax[f], enc_f(mx));
    }
}

// -------- kernel 4: temporal attention (tiny MLP) --------
__global__ void att_kernel(const float* __restrict__ w1,   // [5,20]
                           const float* __restrict__ w2) { // [20,5]
    int tid = threadIdx.x;
    if (tid >= F_TOT) return;
    int b = tid / T_STEPS;
    int t = tid - b * T_STEPS;

    float avgv[T_STEPS], mxv[T_STEPS];
#pragma unroll
    for (int tt = 0; tt < T_STEPS; tt++) {
        avgv[tt] = g_psum[b * T_STEPS + tt] * (1.f / (float)(CH * HW));
        mxv[tt]  = dec_f(g_pmax[b * T_STEPS + tt]);
    }
    float o = 0.f;
#pragma unroll
    for (int j = 0; j < 5; j++) {
        float ha = 0.f, hm = 0.f;
#pragma unroll
        for (int tt = 0; tt < T_STEPS; tt++) {
            float w = w1[j * T_STEPS + tt];
            ha = fmaf(avgv[tt], w, ha);
            hm = fmaf(mxv[tt], w, hm);
        }
        ha = fmaxf(ha, 0.f);
        hm = fmaxf(hm, 0.f);
        o = fmaf(ha + hm, w2[t * 5 + j], o);
    }
    g_att[tid] = 1.f / (1.f + expf(-o));
}

// -------- kernel 5: LIF recurrence --------
__global__ __launch_bounds__(256) void lif_kernel(float* __restrict__ out) {
    int idx = blockIdx.x * blockDim.x + threadIdx.x;   // < B*CH*HW
    int b = idx >> 17;            // / (CH*HW)
    int r = idx & 131071;         // ch*HW + pix
    float h = 0.f;
#pragma unroll
    for (int t = 0; t < T_STEPS; t++) {
        int f = b * T_STEPS + t;
        size_t off = (size_t)f * (CH * HW) + r;
        float v = g_y[off] * g_att[f];
        float u = fmaf(h, 0.3f, v);         // ALPHA = 0.3
        float s = (u >= 0.6f) ? 1.f : 0.f;  // VTH = 0.6
        out[off] = s;
        h = u * (1.f - s);                  // hard reset, VRESET = 0
    }
}

// -------- launch --------
extern "C" void kernel_launch(void* const* d_in, const int* in_sizes, int n_in,
                              void* d_out, int out_size) {
    const float* data   = (const float*)d_in[0];  // [16,20,64,32,32]
    const float* conv_w = (const float*)d_in[1];  // [128,64,3,3]
    const float* conv_b = (const float*)d_in[2];  // [128]
    const float* mlp_w1 = (const float*)d_in[3];  // [5,20]
    const float* mlp_w2 = (const float*)d_in[4];  // [20,5]
    float* out = (float*)d_out;

    init_kernel<<<(F_TOT + 255) / 256, 256>>>();
    wt_kernel<<<(KTOT * CH + 255) / 256, 256>>>(conv_w);
    conv_kernel<<<dim3(8, F_TOT), 256>>>(data, conv_b);
    att_kernel<<<1, F_TOT>>>(mlp_w1, mlp_w2);
    lif_kernel<<<(B_SZ * CH * HW) / 256, 256>>>(out);
}